// round 4
// baseline (speedup 1.0000x reference)
#include <cuda_runtime.h>

#define BSZ 128
#define SEQ 2048
#define NV 64
#define DM 512
#define KC 64
#define NPTS (BSZ*NV)            /* 8192 */
#define PROB_SIZE (NPTS*KC)      /* 524288 */
#define CENT_SIZE (KC*DM)        /* 32768 */
#define XEMB_OFF (PROB_SIZE+CENT_SIZE) /* 557056 */
#define MAX_ITER 10
#define GRID_B 128               /* persistent blocks; chunk = 64 points */
#define PTS_PER_BLK 64

#define SM_TAIL 5136
#define SMEM_TOTAL (CENT_SIZE*4 + SM_TAIL)   /* 136208 B */

typedef unsigned long long ull;

__device__ __align__(16) float g_cent[CENT_SIZE];
__device__ float g_csq[KC];
__device__ int   g_ids[NPTS];
__device__ float g_shift[KC];
__device__ __align__(16) float g_part[GRID_B*CENT_SIZE];  /* 16 MB */
__device__ int   g_pcnt[GRID_B*KC];
__device__ unsigned g_bar_cnt;
__device__ volatile unsigned g_bar_sense;

/* ---------- packed fp32x2 helpers (Blackwell) ---------- */
static __device__ __forceinline__ ull pk2(float lo, float hi){
    ull r;
    asm("mov.b64 %0, {%1, %2};" : "=l"(r)
        : "r"(__float_as_uint(lo)), "r"(__float_as_uint(hi)));
    return r;
}
static __device__ __forceinline__ ull fma2(ull a, ull b, ull c){
    ull d;
    asm("fma.rn.f32x2 %0, %1, %2, %3;" : "=l"(d) : "l"(a), "l"(b), "l"(c));
    return d;
}
static __device__ __forceinline__ void upk2(ull v, float &lo, float &hi){
    unsigned int a, b;
    asm("mov.b64 {%0, %1}, %2;" : "=r"(a), "=r"(b) : "l"(v));
    lo = __uint_as_float(a); hi = __uint_as_float(b);
}

/* ---------- grid-wide sense-reversing barrier (all blocks resident) ---------- */
static __device__ __forceinline__ void grid_sync(unsigned &sense){
    __syncthreads();
    if (threadIdx.x == 0){
        sense ^= 1u;
        __threadfence();
        unsigned t = atomicAdd(&g_bar_cnt, 1u);
        if (t == GRID_B - 1){
            g_bar_cnt = 0;
            __threadfence();
            g_bar_sense = sense;
        } else {
            while (g_bar_sense != sense){}
        }
    }
    __syncthreads();
}

/* ---------- init: copy centroids, reset barrier state ---------- */
__global__ void init_kernel(const float* __restrict__ cents){
    int i = blockIdx.x * blockDim.x + threadIdx.x;
    if (i < CENT_SIZE) g_cent[i] = cents[i];
    if (i == 0){ g_bar_cnt = 0; g_bar_sense = 0; }
}

/* ---------- one-time c_sq for the initial centroids ---------- */
__global__ void csq_kernel(){
    __shared__ float red[128];
    int k = blockIdx.x, t = threadIdx.x;
    float a = 0.f;
    for (int i = t; i < DM; i += 128){ float v = g_cent[k*DM + i]; a = fmaf(v, v, a); }
    red[t] = a; __syncthreads();
    for (int s = 64; s > 0; s >>= 1){ if (t < s) red[t] += red[t+s]; __syncthreads(); }
    if (t == 0) g_csq[k] = red[0];
}

/* ---------- main GEMM: x_emb[n,d] = sum_s x[b,s,v]*W[d,s] + b[d] ----------
   128(M) x 128(N) x 16(K) tiles, 256 threads, f32x2 m-pair-packed accumulators. */
__global__ void __launch_bounds__(256,2) gemm_kernel(const float* __restrict__ x,
                                                     const float* __restrict__ W,
                                                     const float* __restrict__ bias,
                                                     float* __restrict__ xemb){
    __shared__ __align__(16) float As[16][128];
    __shared__ __align__(16) float Bs[16][128];
    const int tid = threadIdx.x;
    const int d0 = blockIdx.x * 128;
    const int n0 = blockIdx.y * 128;

    int a_m[2], a_c[2], a_base[2];
    int b_d[2], b_s4[2], b_base[2];
#pragma unroll
    for (int j = 0; j < 2; j++){
        int q = j*256 + tid;
        a_m[j] = (q & 31) * 4;
        a_c[j] = q >> 5;
        int gn = n0 + a_m[j];
        a_base[j] = (gn >> 6) * (SEQ*NV) + (gn & 63);
        b_d[j]  = q >> 2;
        b_s4[j] = (q & 3) * 4;
        b_base[j] = (d0 + b_d[j]) * SEQ + b_s4[j];
    }

    ull acc[4][8];
#pragma unroll
    for (int m = 0; m < 4; m++)
#pragma unroll
        for (int j = 0; j < 8; j++) acc[m][j] = 0ull;

    const int tr = tid >> 4, tc = tid & 15;
    const int mb = tr * 8, nb = tc * 8;

    float4 ra[2], rb[2];
#pragma unroll
    for (int j = 0; j < 2; j++){
        ra[j] = *(const float4*)(x + a_base[j] + a_c[j]*NV);
        rb[j] = *(const float4*)(W + b_base[j]);
    }

    const int NT = SEQ / 16;
    for (int t = 0; t < NT; t++){
        __syncthreads();
#pragma unroll
        for (int j = 0; j < 2; j++){
            *(float4*)&As[a_c[j]][a_m[j]] = ra[j];
            Bs[b_s4[j]+0][b_d[j]] = rb[j].x;
            Bs[b_s4[j]+1][b_d[j]] = rb[j].y;
            Bs[b_s4[j]+2][b_d[j]] = rb[j].z;
            Bs[b_s4[j]+3][b_d[j]] = rb[j].w;
        }
        __syncthreads();
        if (t + 1 < NT){
            int s0 = (t + 1) * 16;
#pragma unroll
            for (int j = 0; j < 2; j++){
                ra[j] = *(const float4*)(x + a_base[j] + (s0 + a_c[j])*NV);
                rb[j] = *(const float4*)(W + b_base[j] + s0);
            }
        }
#pragma unroll
        for (int k = 0; k < 16; k++){
            ulonglong2 A0 = *(const ulonglong2*)&As[k][mb];
            ulonglong2 A1 = *(const ulonglong2*)&As[k][mb+4];
            ull am[4] = {A0.x, A0.y, A1.x, A1.y};
            float4 b0 = *(const float4*)&Bs[k][nb];
            float4 b1 = *(const float4*)&Bs[k][nb+4];
            ull bb[8];
            bb[0] = pk2(b0.x, b0.x); bb[1] = pk2(b0.y, b0.y);
            bb[2] = pk2(b0.z, b0.z); bb[3] = pk2(b0.w, b0.w);
            bb[4] = pk2(b1.x, b1.x); bb[5] = pk2(b1.y, b1.y);
            bb[6] = pk2(b1.z, b1.z); bb[7] = pk2(b1.w, b1.w);
#pragma unroll
            for (int m = 0; m < 4; m++)
#pragma unroll
                for (int j = 0; j < 8; j++)
                    acc[m][j] = fma2(am[m], bb[j], acc[m][j]);
        }
    }

    float4 bv0 = *(const float4*)&bias[d0 + nb];
    float4 bv1 = *(const float4*)&bias[d0 + nb + 4];
    float bvals[8] = {bv0.x,bv0.y,bv0.z,bv0.w,bv1.x,bv1.y,bv1.z,bv1.w};
#pragma unroll
    for (int m = 0; m < 4; m++){
        float lo[8], hi[8];
#pragma unroll
        for (int j = 0; j < 8; j++){
            upk2(acc[m][j], lo[j], hi[j]);
            lo[j] += bvals[j]; hi[j] += bvals[j];
        }
        int gn = n0 + mb + 2*m;
        float* r0 = xemb + gn*DM + d0 + nb;
        float* r1 = r0 + DM;
        *(float4*)r0     = make_float4(lo[0],lo[1],lo[2],lo[3]);
        *(float4*)(r0+4) = make_float4(lo[4],lo[5],lo[6],lo[7]);
        *(float4*)r1     = make_float4(hi[0],hi[1],hi[2],hi[3]);
        *(float4*)(r1+4) = make_float4(hi[4],hi[5],hi[6],hi[7]);
    }
}

/* ---------- persistent k-means: all 10 iterations + output in ONE kernel ----
   128 blocks x 256 threads, all resident. Each block owns a 64-point chunk.
   Per iteration: A(assign, block-local) -> B(chunk partial sums, smem) ->
   barrier -> C(combine, blocks 0..63) -> barrier.  Cross-block reads use
   __ldcg (L1 never flushed inside one launch). */
__global__ void __launch_bounds__(256,1) kmeans_kernel(const float* __restrict__ xemb,
                                                       float* __restrict__ out){
    extern __shared__ __align__(16) char sm[];
    float* sums = (float*)sm;                               /* [KC*DM], phase B  */
    float (*xs)[68] = (float(*)[68])sm;                     /* phase A overlay   */
    float (*cs)[64] = (float(*)[64])(sm + 64*68*4);
    char* tail = sm + CENT_SIZE*4;
    float* s_xsq     = (float*)tail;                        /* 64 floats  */
    float (*bv)[64]  = (float(*)[64])(tail + 256);
    int   (*bi)[64]  = (int(*)[64])(tail + 1280);
    int*  sids       = (int*)(tail + 2304);                 /* 64 ints    */
    float* reds      = (float*)(tail + 2560);               /* 256 floats */
    float* redc      = (float*)(tail + 3584);               /* 256 floats */
    int*  s_scr      = (int*)(tail + 4608);                 /* 128 ints   */
    int*  s_flag     = (int*)(tail + 5120);

    const int tid = threadIdx.x;
    const int blk = blockIdx.x;
    const int base_p = blk * PTS_PER_BLK;

    /* prologue: x_sq for this block's 64 points (block-local forever) */
    {
        int w = tid >> 5, lane = tid & 31;
        for (int r = w; r < PTS_PER_BLK; r += 8){
            const float4* row = (const float4*)(xemb + (base_p + r)*DM);
            float a = 0.f;
#pragma unroll
            for (int j = 0; j < 4; j++){
                float4 v = row[j*32 + lane];
                a += v.x*v.x + v.y*v.y + v.z*v.z + v.w*v.w;
            }
#pragma unroll
            for (int off = 16; off > 0; off >>= 1) a += __shfl_down_sync(0xffffffffu, a, off);
            if (lane == 0) s_xsq[r] = a;
        }
    }
    __syncthreads();

    unsigned sense = 0;
    int done = 0;

    for (int it = 0; it < MAX_ITER; it++){
        /* evaluate done from previous iteration's shift (sticky, identical in every block) */
        if (it > 0){
            if (tid == 0){
                int dn = *s_flag;
                if (!dn){
                    float s = 0.f;
#pragma unroll
                    for (int k = 0; k < KC; k++) s += __ldcg(&g_shift[k]);
                    if (s < 1e-8f) dn = 1;   /* ||shift|| < 1e-4  <=>  sumsq < 1e-8 */
                }
                *s_flag = dn;
            }
            __syncthreads();
            done = *s_flag;
        } else if (tid == 0){
            *s_flag = 0;
        }

        if (!done){
            /* ---- phase A: assign ids for this block's 64 points ---- */
            const int pl = tid & 63;
            const int g  = tid >> 6;
            ull acc2[16];
#pragma unroll
            for (int i = 0; i < 16; i++) acc2[i] = 0ull;

            for (int d0 = 0; d0 < DM; d0 += 64){
#pragma unroll
                for (int j = 0; j < 4; j++){
                    int q = j*256 + tid;
                    int r = q >> 4;
                    int c4 = (q & 15) * 4;
                    float4 v = *(const float4*)(xemb + (base_p + r)*DM + d0 + c4);
                    *(float4*)&xs[r][c4] = v;
                    float4 w = __ldcg((const float4*)&g_cent[r*DM + d0 + c4]);
                    *(float4*)&cs[r][c4] = w;
                }
                __syncthreads();
#pragma unroll
                for (int dd = 0; dd < 64; dd += 8){
                    ulonglong2 X0 = *(const ulonglong2*)&xs[pl][dd];
                    ulonglong2 X1 = *(const ulonglong2*)&xs[pl][dd+4];
#pragma unroll
                    for (int kk = 0; kk < 16; kk++){
                        const float* cp = &cs[g*16 + kk][dd];
                        ulonglong2 C0 = *(const ulonglong2*)cp;
                        ulonglong2 C1 = *(const ulonglong2*)(cp + 4);
                        ull a = acc2[kk];
                        a = fma2(X0.x, C0.x, a);
                        a = fma2(X0.y, C0.y, a);
                        a = fma2(X1.x, C1.x, a);
                        a = fma2(X1.y, C1.y, a);
                        acc2[kk] = a;
                    }
                }
                __syncthreads();
            }

            float xq = s_xsq[pl];
            float best = 3.4e38f;
            int bk = 0;
#pragma unroll
            for (int kk = 0; kk < 16; kk++){
                int k = g*16 + kk;
                float lo, hi; upk2(acc2[kk], lo, hi);
                float d2v = (xq - 2.0f*(lo + hi)) + __ldcg(&g_csq[k]);
                if (d2v < best){ best = d2v; bk = k; }
            }
            bv[g][pl] = best; bi[g][pl] = bk;
            __syncthreads();
            if (g == 0){
#pragma unroll
                for (int gg = 1; gg < 4; gg++){
                    float v = bv[gg][pl];
                    if (v < best){ best = v; bk = bi[gg][pl]; }
                }
                sids[pl] = bk;
                g_ids[base_p + pl] = bk;
            }
            __syncthreads();

            /* ---- phase B: chunk partial sums in smem (no grid barrier needed) ---- */
#pragma unroll
            for (int i = 0; i < 32; i++)
                *(float4*)&sums[(i*256 + tid)*4] = make_float4(0.f,0.f,0.f,0.f);
            __syncthreads();

            const int d2 = tid * 2;
#pragma unroll 4
            for (int p = 0; p < PTS_PER_BLK; p++){
                int id = sids[p];
                float2 v = *(const float2*)(xemb + (base_p + p)*DM + d2);
                float* srow = &sums[id*DM + d2];
                srow[0] += v.x; srow[1] += v.y;
            }
            __syncthreads();
#pragma unroll
            for (int i = 0; i < 32; i++){
                int f4 = i*256 + tid;
                *(float4*)&g_part[blk*CENT_SIZE + f4*4] = *(const float4*)&sums[f4*4];
            }
            if (tid < KC){
                int c = 0;
#pragma unroll
                for (int p = 0; p < PTS_PER_BLK; p++) c += (sids[p] == tid);
                g_pcnt[blk*KC + tid] = c;
            }
        }
        grid_sync(sense);

        /* ---- phase C: combine -> new centroids + csq + shift (blocks 0..63) ---- */
        if (!done && blk < KC){
            const int k = blk;
            const int d2 = tid * 2;
            float sx = 0.f, sy = 0.f;
#pragma unroll 4
            for (int b = 0; b < GRID_B; b++){
                float2 v = __ldcg((const float2*)&g_part[b*CENT_SIZE + k*DM + d2]);
                sx += v.x; sy += v.y;
            }
            if (tid < GRID_B) s_scr[tid] = __ldcg(&g_pcnt[tid*KC + k]);
            __syncthreads();
            for (int s = 64; s > 0; s >>= 1){
                if (tid < s) s_scr[tid] += s_scr[tid + s];
                __syncthreads();
            }
            int cnt = s_scr[0];

            float old0 = g_cent[k*DM + d2], old1 = g_cent[k*DM + d2 + 1];
            float n0 = (cnt > 0) ? sx / (float)cnt : old0;
            float n1 = (cnt > 0) ? sy / (float)cnt : old1;
            g_cent[k*DM + d2]     = n0;
            g_cent[k*DM + d2 + 1] = n1;
            float df0 = n0 - old0, df1 = n1 - old1;
            reds[tid] = df0*df0 + df1*df1;
            redc[tid] = n0*n0 + n1*n1;
            __syncthreads();
            for (int s = 128; s > 0; s >>= 1){
                if (tid < s){ reds[tid] += reds[tid+s]; redc[tid] += redc[tid+s]; }
                __syncthreads();
            }
            if (tid == 0){ g_shift[k] = reds[0]; g_csq[k] = redc[0]; }
        }
        grid_sync(sense);
    }

    /* ---- epilogue: one-hot prob + centroid copy (32768 threads) ---- */
    const int gt = blk*256 + tid;
    if (gt < NPTS){
        int id = __ldcg(&g_ids[gt]);
        float4* o = (float4*)(out + (size_t)gt*KC);
        int jv = id >> 2, comp = id & 3;
#pragma unroll
        for (int j = 0; j < 16; j++){
            float4 z = make_float4(0.f,0.f,0.f,0.f);
            if (j == jv) (&z.x)[comp] = 1.0f;
            o[j] = z;
        }
    }
    out[PROB_SIZE + gt] = __ldcg(&g_cent[gt]);
}

extern "C" void kernel_launch(void* const* d_in, const int* in_sizes, int n_in,
                              void* d_out, int out_size){
    const float* x     = (const float*)d_in[0];   /* [128,2048,64] */
    const float* W     = (const float*)d_in[1];   /* [512,2048]    */
    const float* bias  = (const float*)d_in[2];   /* [512]         */
    const float* cents = (const float*)d_in[3];   /* [64,512]      */
    float* out  = (float*)d_out;
    float* xemb = out + XEMB_OFF;

    cudaFuncSetAttribute((const void*)kmeans_kernel,
                         cudaFuncAttributeMaxDynamicSharedMemorySize, SMEM_TOTAL);

    init_kernel<<<(CENT_SIZE + 255)/256, 256>>>(cents);
    gemm_kernel<<<dim3(DM/128, NPTS/128), 256>>>(x, W, bias, xemb);
    csq_kernel<<<KC, 128>>>();
    kmeans_kernel<<<GRID_B, 256, SMEM_TOTAL>>>(xemb, out);
}

// round 8
// speedup vs baseline: 1.1783x; 1.1783x over previous
#include <cuda_runtime.h>

#define BSZ 128
#define SEQ 2048
#define NV 64
#define DM 512
#define KC 64
#define NPTS (BSZ*NV)            /* 8192 */
#define PROB_SIZE (NPTS*KC)      /* 524288 */
#define CENT_SIZE (KC*DM)        /* 32768 */
#define XEMB_OFF (PROB_SIZE+CENT_SIZE) /* 557056 */
#define MAX_ITER 10
#define NCHUNK 128               /* one chunk (64 points) per assign block */

#define SMEM_AP (CENT_SIZE*4 + 4864)   /* 135936 B dynamic smem for fused kernel */

typedef unsigned long long ull;

__device__ __align__(16) float g_cent[CENT_SIZE];
__device__ float g_csq[KC];
__device__ int   g_ids[NPTS];
__device__ float g_shift[KC];
__device__ __align__(16) float g_part[NCHUNK*CENT_SIZE];  /* 16 MB */
__device__ int   g_pcnt[NCHUNK*KC];
__device__ int   g_done;
__device__ int   g_ctr[MAX_ITER];

/* ---------- packed fp32x2 helpers (Blackwell) ---------- */
static __device__ __forceinline__ ull pk2(float lo, float hi){
    ull r;
    asm("mov.b64 %0, {%1, %2};" : "=l"(r)
        : "r"(__float_as_uint(lo)), "r"(__float_as_uint(hi)));
    return r;
}
static __device__ __forceinline__ ull fma2(ull a, ull b, ull c){
    ull d;
    asm("fma.rn.f32x2 %0, %1, %2, %3;" : "=l"(d) : "l"(a), "l"(b), "l"(c));
    return d;
}
static __device__ __forceinline__ void upk2(ull v, float &lo, float &hi){
    unsigned int a, b;
    asm("mov.b64 {%0, %1}, %2;" : "=r"(a), "=r"(b) : "l"(v));
    lo = __uint_as_float(a); hi = __uint_as_float(b);
}

/* ---------- prep: copy centroids + csq + reset counters (64 blocks x 256) ---------- */
__global__ void prep_kernel(const float* __restrict__ cents){
    __shared__ float red[256];
    const int k = blockIdx.x, t = threadIdx.x;
    float2 v = ((const float2*)(cents + k*DM))[t];
    ((float2*)(g_cent + k*DM))[t] = v;
    red[t] = v.x*v.x + v.y*v.y;
    __syncthreads();
    for (int s = 128; s > 0; s >>= 1){ if (t < s) red[t] += red[t+s]; __syncthreads(); }
    if (t == 0) g_csq[k] = red[0];
    if (k == 0){
        if (t < MAX_ITER) g_ctr[t] = 0;
        if (t == 0) g_done = 0;
    }
}

/* ---------- main GEMM: x_emb[n,d] = sum_s x[b,s,v]*W[d,s] + b[d] ----------
   128(M) x 128(N) x 16(K) tiles, 256 threads, f32x2 m-pair-packed accumulators,
   double-buffered smem (one sync per k-tile). */
__global__ void __launch_bounds__(256,2) gemm_kernel(const float* __restrict__ x,
                                                     const float* __restrict__ W,
                                                     const float* __restrict__ bias,
                                                     float* __restrict__ xemb){
    __shared__ __align__(16) float As[2][16][128];
    __shared__ __align__(16) float Bs[2][16][128];
    const int tid = threadIdx.x;
    const int d0 = blockIdx.x * 128;
    const int n0 = blockIdx.y * 128;

    int a_m[2], a_c[2], a_base[2];
    int b_d[2], b_s4[2], b_base[2];
#pragma unroll
    for (int j = 0; j < 2; j++){
        int q = j*256 + tid;
        a_m[j] = (q & 31) * 4;
        a_c[j] = q >> 5;
        int gn = n0 + a_m[j];
        a_base[j] = (gn >> 6) * (SEQ*NV) + (gn & 63);
        b_d[j]  = q >> 2;
        b_s4[j] = (q & 3) * 4;
        b_base[j] = (d0 + b_d[j]) * SEQ + b_s4[j];
    }

    ull acc[4][8];
#pragma unroll
    for (int m = 0; m < 4; m++)
#pragma unroll
        for (int j = 0; j < 8; j++) acc[m][j] = 0ull;

    const int tr = tid >> 4, tc = tid & 15;
    const int mb = tr * 8, nb = tc * 8;

    /* prologue: tile 0 into buffer 0 */
    float4 ra[2], rb[2];
#pragma unroll
    for (int j = 0; j < 2; j++){
        ra[j] = *(const float4*)(x + a_base[j] + a_c[j]*NV);
        rb[j] = *(const float4*)(W + b_base[j]);
    }
#pragma unroll
    for (int j = 0; j < 2; j++){
        *(float4*)&As[0][a_c[j]][a_m[j]] = ra[j];
        Bs[0][b_s4[j]+0][b_d[j]] = rb[j].x;
        Bs[0][b_s4[j]+1][b_d[j]] = rb[j].y;
        Bs[0][b_s4[j]+2][b_d[j]] = rb[j].z;
        Bs[0][b_s4[j]+3][b_d[j]] = rb[j].w;
    }
    __syncthreads();

    const int NT = SEQ / 16;
    for (int t = 0; t < NT; t++){
        const int cur = t & 1;
        if (t + 1 < NT){
            int s0 = (t + 1) * 16;
#pragma unroll
            for (int j = 0; j < 2; j++){
                ra[j] = *(const float4*)(x + a_base[j] + (s0 + a_c[j])*NV);
                rb[j] = *(const float4*)(W + b_base[j] + s0);
            }
        }
#pragma unroll
        for (int k = 0; k < 16; k++){
            ulonglong2 A0 = *(const ulonglong2*)&As[cur][k][mb];
            ulonglong2 A1 = *(const ulonglong2*)&As[cur][k][mb+4];
            ull am[4] = {A0.x, A0.y, A1.x, A1.y};
            float4 b0 = *(const float4*)&Bs[cur][k][nb];
            float4 b1 = *(const float4*)&Bs[cur][k][nb+4];
            ull bb[8];
            bb[0] = pk2(b0.x, b0.x); bb[1] = pk2(b0.y, b0.y);
            bb[2] = pk2(b0.z, b0.z); bb[3] = pk2(b0.w, b0.w);
            bb[4] = pk2(b1.x, b1.x); bb[5] = pk2(b1.y, b1.y);
            bb[6] = pk2(b1.z, b1.z); bb[7] = pk2(b1.w, b1.w);
#pragma unroll
            for (int m = 0; m < 4; m++)
#pragma unroll
                for (int j = 0; j < 8; j++)
                    acc[m][j] = fma2(am[m], bb[j], acc[m][j]);
        }
        if (t + 1 < NT){
            const int nxt = cur ^ 1;
#pragma unroll
            for (int j = 0; j < 2; j++){
                *(float4*)&As[nxt][a_c[j]][a_m[j]] = ra[j];
                Bs[nxt][b_s4[j]+0][b_d[j]] = rb[j].x;
                Bs[nxt][b_s4[j]+1][b_d[j]] = rb[j].y;
                Bs[nxt][b_s4[j]+2][b_d[j]] = rb[j].z;
                Bs[nxt][b_s4[j]+3][b_d[j]] = rb[j].w;
            }
        }
        __syncthreads();
    }

    float4 bv0 = *(const float4*)&bias[d0 + nb];
    float4 bv1 = *(const float4*)&bias[d0 + nb + 4];
    float bvals[8] = {bv0.x,bv0.y,bv0.z,bv0.w,bv1.x,bv1.y,bv1.z,bv1.w};
#pragma unroll
    for (int m = 0; m < 4; m++){
        float lo[8], hi[8];
#pragma unroll
        for (int j = 0; j < 8; j++){
            upk2(acc[m][j], lo[j], hi[j]);
            lo[j] += bvals[j]; hi[j] += bvals[j];
        }
        int gn = n0 + mb + 2*m;
        float* r0 = xemb + gn*DM + d0 + nb;
        float* r1 = r0 + DM;
        *(float4*)r0     = make_float4(lo[0],lo[1],lo[2],lo[3]);
        *(float4*)(r0+4) = make_float4(lo[4],lo[5],lo[6],lo[7]);
        *(float4*)r1     = make_float4(hi[0],hi[1],hi[2],hi[3]);
        *(float4*)(r1+4) = make_float4(hi[4],hi[5],hi[6],hi[7]);
    }
}

/* ---------- fused assign + chunk-partial kernel ----------
   128 blocks x 512 threads, block owns 64 points.
   Phase A: argmin over 64 centroids (8 groups of 8); x_sq computed in-flight
   by the g==0 warps from the same smem tiles.
   Phase B: deterministic per-chunk segment sums in smem -> g_part. */
__global__ void __launch_bounds__(512,1) assign_partial_kernel(const float* __restrict__ xemb){
    if (g_done) return;
    extern __shared__ __align__(16) char sm[];
    float* sums = (float*)sm;                         /* [KC*DM] phase B        */
    float (*xs)[68] = (float(*)[68])sm;               /* phase A overlay        */
    float (*cs)[64] = (float(*)[64])(sm + 64*68*4);
    char* tail = sm + CENT_SIZE*4;
    float* s_xsq    = (float*)tail;                   /* 64 floats              */
    float (*bv)[64] = (float(*)[64])(tail + 256);     /* 8x64 floats            */
    int   (*bi)[64] = (int(*)[64])(tail + 2304);      /* 8x64 ints              */
    int*  sids      = (int*)(tail + 4352);            /* 64 ints                */

    const int tid = threadIdx.x;
    const int blk = blockIdx.x;
    const int base_p = blk * 64;
    const int pl = tid & 63;
    const int g  = tid >> 6;                          /* 0..7 */

    /* ---- phase A ---- */
    ull acc2[8];
#pragma unroll
    for (int i = 0; i < 8; i++) acc2[i] = 0ull;
    ull xacc = 0ull;

    for (int d0 = 0; d0 < DM; d0 += 64){
#pragma unroll
        for (int j = 0; j < 2; j++){
            int q = j*512 + tid;          /* 0..1023 */
            int r = q >> 4;               /* 0..63   */
            int c4 = (q & 15) * 4;
            float4 v = *(const float4*)(xemb + (base_p + r)*DM + d0 + c4);
            *(float4*)&xs[r][c4] = v;
            float4 w = *(const float4*)(&g_cent[r*DM + d0 + c4]);
            *(float4*)&cs[r][c4] = w;
        }
        __syncthreads();
#pragma unroll
        for (int dd = 0; dd < 64; dd += 8){
            ulonglong2 X0 = *(const ulonglong2*)&xs[pl][dd];
            ulonglong2 X1 = *(const ulonglong2*)&xs[pl][dd+4];
#pragma unroll
            for (int kk = 0; kk < 8; kk++){
                const float* cp = &cs[g*8 + kk][dd];
                ulonglong2 C0 = *(const ulonglong2*)cp;
                ulonglong2 C1 = *(const ulonglong2*)(cp + 4);
                ull a = acc2[kk];
                a = fma2(X0.x, C0.x, a);
                a = fma2(X0.y, C0.y, a);
                a = fma2(X1.x, C1.x, a);
                a = fma2(X1.y, C1.y, a);
                acc2[kk] = a;
            }
            if (g == 0){                  /* warps 0-1: x_sq in-flight */
                xacc = fma2(X0.x, X0.x, xacc);
                xacc = fma2(X0.y, X0.y, xacc);
                xacc = fma2(X1.x, X1.x, xacc);
                xacc = fma2(X1.y, X1.y, xacc);
            }
        }
        __syncthreads();
    }
    if (g == 0){
        float lo, hi; upk2(xacc, lo, hi);
        s_xsq[pl] = lo + hi;
    }
    __syncthreads();

    float xq = s_xsq[pl];
    float best = 3.4e38f;
    int bk = 0;
#pragma unroll
    for (int kk = 0; kk < 8; kk++){
        int k = g*8 + kk;
        float lo, hi; upk2(acc2[kk], lo, hi);
        float d2v = (xq - 2.0f*(lo + hi)) + g_csq[k];
        if (d2v < best){ best = d2v; bk = k; }
    }
    bv[g][pl] = best; bi[g][pl] = bk;
    __syncthreads();
    if (g == 0){
#pragma unroll
        for (int gg = 1; gg < 8; gg++){
            float v = bv[gg][pl];
            if (v < best){ best = v; bk = bi[gg][pl]; }
        }
        sids[pl] = bk;
        g_ids[base_p + pl] = bk;
    }
    __syncthreads();

    /* ---- phase B: chunk partial sums (deterministic ascending p) ---- */
#pragma unroll
    for (int i = 0; i < 16; i++)
        *(float4*)&sums[(i*512 + tid)*4] = make_float4(0.f,0.f,0.f,0.f);
    __syncthreads();

    const int d = tid;                    /* 0..511: one dim per thread */
#pragma unroll 4
    for (int p = 0; p < 64; p++){
        int id = sids[p];
        sums[id*DM + d] += xemb[(base_p + p)*DM + d];
    }
    __syncthreads();
#pragma unroll
    for (int i = 0; i < 16; i++){
        int f4 = i*512 + tid;
        *(float4*)&g_part[blk*CENT_SIZE + f4*4] = *(const float4*)&sums[f4*4];
    }
    if (tid < KC){
        int c = 0;
#pragma unroll
        for (int p = 0; p < 64; p++) c += (sids[p] == tid);
        g_pcnt[blk*KC + tid] = c;
    }
}

/* ---------- combine: new centroids + csq + shift + done flag (64 blocks x 256) ---------- */
__global__ void __launch_bounds__(256) combine_kernel(int iter){
    if (g_done) return;
    __shared__ float reds[256];
    __shared__ float redc[256];
    __shared__ int   s_scr[256];
    const int k = blockIdx.x, t = threadIdx.x;
    const int d2 = t * 2;
    float sx = 0.f, sy = 0.f;
#pragma unroll 4
    for (int b = 0; b < NCHUNK; b++){
        float2 v = *(const float2*)&g_part[b*CENT_SIZE + k*DM + d2];
        sx += v.x; sy += v.y;
    }
    s_scr[t] = (t < NCHUNK) ? g_pcnt[t*KC + k] : 0;
    __syncthreads();
    for (int s = 128; s > 0; s >>= 1){ if (t < s) s_scr[t] += s_scr[t+s]; __syncthreads(); }
    int cnt = s_scr[0];

    float old0 = g_cent[k*DM + d2], old1 = g_cent[k*DM + d2 + 1];
    float n0 = (cnt > 0) ? sx / (float)cnt : old0;
    float n1 = (cnt > 0) ? sy / (float)cnt : old1;
    g_cent[k*DM + d2]     = n0;
    g_cent[k*DM + d2 + 1] = n1;
    float df0 = n0 - old0, df1 = n1 - old1;
    reds[t] = df0*df0 + df1*df1;
    redc[t] = n0*n0 + n1*n1;
    __syncthreads();
    for (int s = 128; s > 0; s >>= 1){
        if (t < s){ reds[t] += reds[t+s]; redc[t] += redc[t+s]; }
        __syncthreads();
    }
    if (t == 0){ g_shift[k] = reds[0]; g_csq[k] = redc[0]; }
    __threadfence();
    __syncthreads();
    if (t == 0){
        int c = atomicAdd(&g_ctr[iter], 1);
        if (c == KC - 1){
            __threadfence();
            float s = 0.f;
            for (int k2 = 0; k2 < KC; k2++) s += g_shift[k2];
            if (s < 1e-8f) g_done = 1;   /* ||shift|| < 1e-4 <=> sumsq < 1e-8 */
        }
    }
}

/* ---------- outputs: one-hot prob + centroid copy (128 blocks x 256) ---------- */
__global__ void output_kernel(float* __restrict__ out){
    const int gt = blockIdx.x*256 + threadIdx.x;    /* 0..32767 */
    if (gt < NPTS){
        int id = g_ids[gt];
        float4* o = (float4*)(out + (size_t)gt*KC);
        int jv = id >> 2, comp = id & 3;
#pragma unroll
        for (int j = 0; j < 16; j++){
            float4 z = make_float4(0.f,0.f,0.f,0.f);
            if (j == jv) (&z.x)[comp] = 1.0f;
            o[j] = z;
        }
    }
    out[PROB_SIZE + gt] = g_cent[gt];
}

extern "C" void kernel_launch(void* const* d_in, const int* in_sizes, int n_in,
                              void* d_out, int out_size){
    const float* x     = (const float*)d_in[0];   /* [128,2048,64] */
    const float* W     = (const float*)d_in[1];   /* [512,2048]    */
    const float* bias  = (const float*)d_in[2];   /* [512]         */
    const float* cents = (const float*)d_in[3];   /* [64,512]      */
    float* out  = (float*)d_out;
    float* xemb = out + XEMB_OFF;

    cudaFuncSetAttribute((const void*)assign_partial_kernel,
                         cudaFuncAttributeMaxDynamicSharedMemorySize, SMEM_AP);

    prep_kernel<<<KC, 256>>>(cents);
    gemm_kernel<<<dim3(DM/128, NPTS/128), 256>>>(x, W, bias, xemb);

    for (int it = 0; it < MAX_ITER; it++){
        assign_partial_kernel<<<NCHUNK, 512, SMEM_AP>>>(xemb);
        combine_kernel<<<KC, 256>>>(it);
    }
    output_kernel<<<NPTS/64, 256>>>(out);
}

// round 9
// speedup vs baseline: 1.2517x; 1.0623x over previous
#include <cuda_runtime.h>

#define BSZ 128
#define SEQ 2048
#define NV 64
#define DM 512
#define KC 64
#define NPTS (BSZ*NV)            /* 8192 */
#define PROB_SIZE (NPTS*KC)      /* 524288 */
#define CENT_SIZE (KC*DM)        /* 32768 */
#define XEMB_OFF (PROB_SIZE+CENT_SIZE) /* 557056 */
#define MAX_ITER 10
#define NCHUNK 128               /* one chunk (64 points) per assign block */

#define SMEM_AP (CENT_SIZE*4 + 4880)   /* 135952 B dynamic smem for fused kernel */

typedef unsigned long long ull;

__device__ __align__(16) float g_cent[CENT_SIZE];
__device__ float g_csqp[KC*4];                    /* per-(k,dg) csq partials   */
__device__ float g_shiftp[KC*4];                  /* per-(k,dg) shift partials */
__device__ int   g_ids[NPTS];
__device__ __align__(16) float g_part[KC*NCHUNK*DM];  /* [k][chunk][d], 16 MB */
__device__ int   g_pcnt[KC*NCHUNK];               /* [k][chunk] */
__device__ int   g_done;

/* ---------- packed fp32x2 helpers (Blackwell) ---------- */
static __device__ __forceinline__ ull pk2(float lo, float hi){
    ull r;
    asm("mov.b64 %0, {%1, %2};" : "=l"(r)
        : "r"(__float_as_uint(lo)), "r"(__float_as_uint(hi)));
    return r;
}
static __device__ __forceinline__ ull fma2(ull a, ull b, ull c){
    ull d;
    asm("fma.rn.f32x2 %0, %1, %2, %3;" : "=l"(d) : "l"(a), "l"(b), "l"(c));
    return d;
}
static __device__ __forceinline__ void upk2(ull v, float &lo, float &hi){
    unsigned int a, b;
    asm("mov.b64 {%0, %1}, %2;" : "=r"(a), "=r"(b) : "l"(v));
    lo = __uint_as_float(a); hi = __uint_as_float(b);
}

/* ---------- prep: copy centroids, per-(k,dg) csq partials, reset shift ----
   grid (KC,4) x 128 threads, mirroring combine's reduction layout. */
__global__ void prep_kernel(const float* __restrict__ cents){
    __shared__ float red[128];
    const int k = blockIdx.x, dg = blockIdx.y, t = threadIdx.x;
    const int dim = dg*128 + t;
    float c = cents[k*DM + dim];
    g_cent[k*DM + dim] = c;
    red[t] = c*c;
    __syncthreads();
    for (int s = 64; s > 0; s >>= 1){ if (t < s) red[t] += red[t+s]; __syncthreads(); }
    if (t == 0){
        g_csqp[k*4 + dg] = red[0];
        g_shiftp[k*4 + dg] = 1.0f;     /* "not converged" sentinel */
    }
}

/* ---------- main GEMM: x_emb[n,d] = sum_s x[b,s,v]*W[d,s] + b[d] ----------
   128(M) x 128(N) x 16(K) tiles, 256 threads, f32x2 m-pair-packed accumulators,
   double-buffered smem (one sync per k-tile). */
__global__ void __launch_bounds__(256,2) gemm_kernel(const float* __restrict__ x,
                                                     const float* __restrict__ W,
                                                     const float* __restrict__ bias,
                                                     float* __restrict__ xemb){
    __shared__ __align__(16) float As[2][16][128];
    __shared__ __align__(16) float Bs[2][16][128];
    const int tid = threadIdx.x;
    const int d0 = blockIdx.x * 128;
    const int n0 = blockIdx.y * 128;

    int a_m[2], a_c[2], a_base[2];
    int b_d[2], b_s4[2], b_base[2];
#pragma unroll
    for (int j = 0; j < 2; j++){
        int q = j*256 + tid;
        a_m[j] = (q & 31) * 4;
        a_c[j] = q >> 5;
        int gn = n0 + a_m[j];
        a_base[j] = (gn >> 6) * (SEQ*NV) + (gn & 63);
        b_d[j]  = q >> 2;
        b_s4[j] = (q & 3) * 4;
        b_base[j] = (d0 + b_d[j]) * SEQ + b_s4[j];
    }

    ull acc[4][8];
#pragma unroll
    for (int m = 0; m < 4; m++)
#pragma unroll
        for (int j = 0; j < 8; j++) acc[m][j] = 0ull;

    const int tr = tid >> 4, tc = tid & 15;
    const int mb = tr * 8, nb = tc * 8;

    float4 ra[2], rb[2];
#pragma unroll
    for (int j = 0; j < 2; j++){
        ra[j] = *(const float4*)(x + a_base[j] + a_c[j]*NV);
        rb[j] = *(const float4*)(W + b_base[j]);
    }
#pragma unroll
    for (int j = 0; j < 2; j++){
        *(float4*)&As[0][a_c[j]][a_m[j]] = ra[j];
        Bs[0][b_s4[j]+0][b_d[j]] = rb[j].x;
        Bs[0][b_s4[j]+1][b_d[j]] = rb[j].y;
        Bs[0][b_s4[j]+2][b_d[j]] = rb[j].z;
        Bs[0][b_s4[j]+3][b_d[j]] = rb[j].w;
    }
    __syncthreads();

    const int NT = SEQ / 16;
    for (int t = 0; t < NT; t++){
        const int cur = t & 1;
        if (t + 1 < NT){
            int s0 = (t + 1) * 16;
#pragma unroll
            for (int j = 0; j < 2; j++){
                ra[j] = *(const float4*)(x + a_base[j] + (s0 + a_c[j])*NV);
                rb[j] = *(const float4*)(W + b_base[j] + s0);
            }
        }
#pragma unroll
        for (int k = 0; k < 16; k++){
            ulonglong2 A0 = *(const ulonglong2*)&As[cur][k][mb];
            ulonglong2 A1 = *(const ulonglong2*)&As[cur][k][mb+4];
            ull am[4] = {A0.x, A0.y, A1.x, A1.y};
            float4 b0 = *(const float4*)&Bs[cur][k][nb];
            float4 b1 = *(const float4*)&Bs[cur][k][nb+4];
            ull bb[8];
            bb[0] = pk2(b0.x, b0.x); bb[1] = pk2(b0.y, b0.y);
            bb[2] = pk2(b0.z, b0.z); bb[3] = pk2(b0.w, b0.w);
            bb[4] = pk2(b1.x, b1.x); bb[5] = pk2(b1.y, b1.y);
            bb[6] = pk2(b1.z, b1.z); bb[7] = pk2(b1.w, b1.w);
#pragma unroll
            for (int m = 0; m < 4; m++)
#pragma unroll
                for (int j = 0; j < 8; j++)
                    acc[m][j] = fma2(am[m], bb[j], acc[m][j]);
        }
        if (t + 1 < NT){
            const int nxt = cur ^ 1;
#pragma unroll
            for (int j = 0; j < 2; j++){
                *(float4*)&As[nxt][a_c[j]][a_m[j]] = ra[j];
                Bs[nxt][b_s4[j]+0][b_d[j]] = rb[j].x;
                Bs[nxt][b_s4[j]+1][b_d[j]] = rb[j].y;
                Bs[nxt][b_s4[j]+2][b_d[j]] = rb[j].z;
                Bs[nxt][b_s4[j]+3][b_d[j]] = rb[j].w;
            }
        }
        __syncthreads();
    }

    float4 bv0 = *(const float4*)&bias[d0 + nb];
    float4 bv1 = *(const float4*)&bias[d0 + nb + 4];
    float bvals[8] = {bv0.x,bv0.y,bv0.z,bv0.w,bv1.x,bv1.y,bv1.z,bv1.w};
#pragma unroll
    for (int m = 0; m < 4; m++){
        float lo[8], hi[8];
#pragma unroll
        for (int j = 0; j < 8; j++){
            upk2(acc[m][j], lo[j], hi[j]);
            lo[j] += bvals[j]; hi[j] += bvals[j];
        }
        int gn = n0 + mb + 2*m;
        float* r0 = xemb + gn*DM + d0 + nb;
        float* r1 = r0 + DM;
        *(float4*)r0     = make_float4(lo[0],lo[1],lo[2],lo[3]);
        *(float4*)(r0+4) = make_float4(lo[4],lo[5],lo[6],lo[7]);
        *(float4*)r1     = make_float4(hi[0],hi[1],hi[2],hi[3]);
        *(float4*)(r1+4) = make_float4(hi[4],hi[5],hi[6],hi[7]);
    }
}

/* ---------- fused assign + chunk-partial kernel ----------
   128 blocks x 512 threads, block owns 64 points.
   Prologue: done flag from shift partials (warp 0) + csq from partials.
   Phase A: argmin over 64 centroids (8 groups of 8); x_sq in-flight.
   Phase B: deterministic per-chunk segment sums in smem -> g_part. */
__global__ void __launch_bounds__(512,1) assign_partial_kernel(const float* __restrict__ xemb){
    extern __shared__ __align__(16) char sm[];
    float* sums = (float*)sm;                         /* [KC*DM] phase B        */
    float (*xs)[68] = (float(*)[68])sm;               /* phase A overlay        */
    float (*cs)[64] = (float(*)[64])(sm + 64*68*4);
    char* tail = sm + CENT_SIZE*4;
    float* s_xsq    = (float*)tail;                   /* 64 floats              */
    float (*bv)[64] = (float(*)[64])(tail + 256);     /* 8x64 floats            */
    int   (*bi)[64] = (int(*)[64])(tail + 2304);      /* 8x64 ints              */
    int*  sids      = (int*)(tail + 4352);            /* 64 ints                */
    float* s_csq    = (float*)(tail + 4608);          /* 64 floats              */
    int*  s_done    = (int*)(tail + 4864);

    const int tid = threadIdx.x;
    const int blk = blockIdx.x;
    const int base_p = blk * 64;
    const int pl = tid & 63;
    const int g  = tid >> 6;                          /* 0..7 */

    /* ---- prologue: done flag (deterministic) + csq gather ---- */
    if (tid < 32){
        float s = 0.f;
#pragma unroll
        for (int j = 0; j < 8; j++) s += g_shiftp[tid + j*32];
#pragma unroll
        for (int off = 16; off > 0; off >>= 1) s += __shfl_down_sync(0xffffffffu, s, off);
        if (tid == 0){
            int dn = (s < 1e-8f) ? 1 : 0;   /* ||shift|| < 1e-4 <=> sumsq < 1e-8 */
            *s_done = dn;
            g_done = dn;
        }
    } else if (tid >= 64 && tid < 128){
        int k = tid - 64;
        const float* cp = &g_csqp[k*4];
        s_csq[k] = ((cp[0] + cp[1]) + cp[2]) + cp[3];
    }
    __syncthreads();
    if (*s_done) return;

    /* ---- phase A ---- */
    ull acc2[8];
#pragma unroll
    for (int i = 0; i < 8; i++) acc2[i] = 0ull;
    ull xacc = 0ull;

    for (int d0 = 0; d0 < DM; d0 += 64){
#pragma unroll
        for (int j = 0; j < 2; j++){
            int q = j*512 + tid;          /* 0..1023 */
            int r = q >> 4;               /* 0..63   */
            int c4 = (q & 15) * 4;
            float4 v = *(const float4*)(xemb + (base_p + r)*DM + d0 + c4);
            *(float4*)&xs[r][c4] = v;
            float4 w = *(const float4*)(&g_cent[r*DM + d0 + c4]);
            *(float4*)&cs[r][c4] = w;
        }
        __syncthreads();
#pragma unroll
        for (int dd = 0; dd < 64; dd += 8){
            ulonglong2 X0 = *(const ulonglong2*)&xs[pl][dd];
            ulonglong2 X1 = *(const ulonglong2*)&xs[pl][dd+4];
#pragma unroll
            for (int kk = 0; kk < 8; kk++){
                const float* cp = &cs[g*8 + kk][dd];
                ulonglong2 C0 = *(const ulonglong2*)cp;
                ulonglong2 C1 = *(const ulonglong2*)(cp + 4);
                ull a = acc2[kk];
                a = fma2(X0.x, C0.x, a);
                a = fma2(X0.y, C0.y, a);
                a = fma2(X1.x, C1.x, a);
                a = fma2(X1.y, C1.y, a);
                acc2[kk] = a;
            }
            if (g == 0){                  /* warps 0-1: x_sq in-flight */
                xacc = fma2(X0.x, X0.x, xacc);
                xacc = fma2(X0.y, X0.y, xacc);
                xacc = fma2(X1.x, X1.x, xacc);
                xacc = fma2(X1.y, X1.y, xacc);
            }
        }
        __syncthreads();
    }
    if (g == 0){
        float lo, hi; upk2(xacc, lo, hi);
        s_xsq[pl] = lo + hi;
    }
    __syncthreads();

    float xq = s_xsq[pl];
    float best = 3.4e38f;
    int bk = 0;
#pragma unroll
    for (int kk = 0; kk < 8; kk++){
        int k = g*8 + kk;
        float lo, hi; upk2(acc2[kk], lo, hi);
        float d2v = (xq - 2.0f*(lo + hi)) + s_csq[k];
        if (d2v < best){ best = d2v; bk = k; }
    }
    bv[g][pl] = best; bi[g][pl] = bk;
    __syncthreads();
    if (g == 0){
#pragma unroll
        for (int gg = 1; gg < 8; gg++){
            float v = bv[gg][pl];
            if (v < best){ best = v; bk = bi[gg][pl]; }
        }
        sids[pl] = bk;
        g_ids[base_p + pl] = bk;
    }
    __syncthreads();

    /* ---- phase B: chunk partial sums (deterministic ascending p) ---- */
#pragma unroll
    for (int i = 0; i < 16; i++)
        *(float4*)&sums[(i*512 + tid)*4] = make_float4(0.f,0.f,0.f,0.f);
    __syncthreads();

    const int d = tid;                    /* 0..511: one dim per thread */
#pragma unroll 4
    for (int p = 0; p < 64; p++){
        int id = sids[p];
        sums[id*DM + d] += xemb[(base_p + p)*DM + d];
    }
    __syncthreads();
    /* write to transposed layout g_part[k][blk][d] */
#pragma unroll
    for (int i = 0; i < 16; i++){
        int f4 = i*512 + tid;             /* 0..8191 */
        int k  = f4 >> 7;                 /* 0..63   */
        int d4 = f4 & 127;                /* 0..127  */
        *(float4*)&g_part[(k*NCHUNK + blk)*DM + d4*4] = *(const float4*)&sums[f4*4];
    }
    if (tid < KC){
        int c = 0;
#pragma unroll
        for (int p = 0; p < 64; p++) c += (sids[p] == tid);
        g_pcnt[tid*NCHUNK + blk] = c;
    }
}

/* ---------- combine: grid (KC,4) x 128 threads, one dim per thread ----------
   Per-dim chunk order ascending b (identical association to R4). */
__global__ void __launch_bounds__(128) combine_kernel(){
    if (g_done) return;
    __shared__ int   scr[128];
    __shared__ float reds[128];
    __shared__ float redc[128];
    const int k = blockIdx.x, dg = blockIdx.y, t = threadIdx.x;
    const int dim = dg*128 + t;
    const float* base = &g_part[(size_t)k*NCHUNK*DM + dim];

    float s = 0.f;
#pragma unroll 8
    for (int b = 0; b < NCHUNK; b++) s += base[b*DM];

    scr[t] = g_pcnt[k*NCHUNK + t];
    __syncthreads();
    for (int r = 64; r > 0; r >>= 1){ if (t < r) scr[t] += scr[t+r]; __syncthreads(); }
    int cnt = scr[0];

    float old = g_cent[k*DM + dim];
    float nc = (cnt > 0) ? s / (float)cnt : old;
    g_cent[k*DM + dim] = nc;
    float df = nc - old;
    reds[t] = df*df;
    redc[t] = nc*nc;
    __syncthreads();
    for (int r = 64; r > 0; r >>= 1){
        if (t < r){ reds[t] += reds[t+r]; redc[t] += redc[t+r]; }
        __syncthreads();
    }
    if (t == 0){
        g_shiftp[k*4 + dg] = reds[0];
        g_csqp[k*4 + dg]  = redc[0];
    }
}

/* ---------- outputs: one-hot prob + centroid copy (128 blocks x 256) ---------- */
__global__ void output_kernel(float* __restrict__ out){
    const int gt = blockIdx.x*256 + threadIdx.x;    /* 0..32767 */
    if (gt < NPTS){
        int id = g_ids[gt];
        float4* o = (float4*)(out + (size_t)gt*KC);
        int jv = id >> 2, comp = id & 3;
#pragma unroll
        for (int j = 0; j < 16; j++){
            float4 z = make_float4(0.f,0.f,0.f,0.f);
            if (j == jv) (&z.x)[comp] = 1.0f;
            o[j] = z;
        }
    }
    out[PROB_SIZE + gt] = g_cent[gt];
}

extern "C" void kernel_launch(void* const* d_in, const int* in_sizes, int n_in,
                              void* d_out, int out_size){
    const float* x     = (const float*)d_in[0];   /* [128,2048,64] */
    const float* W     = (const float*)d_in[1];   /* [512,2048]    */
    const float* bias  = (const float*)d_in[2];   /* [512]         */
    const float* cents = (const float*)d_in[3];   /* [64,512]      */
    float* out  = (float*)d_out;
    float* xemb = out + XEMB_OFF;

    cudaFuncSetAttribute((const void*)assign_partial_kernel,
                         cudaFuncAttributeMaxDynamicSharedMemorySize, SMEM_AP);

    prep_kernel<<<dim3(KC,4), 128>>>(cents);
    gemm_kernel<<<dim3(DM/128, NPTS/128), 256>>>(x, W, bias, xemb);

    for (int it = 0; it < MAX_ITER; it++){
        assign_partial_kernel<<<NCHUNK, 512, SMEM_AP>>>(xemb);
        combine_kernel<<<dim3(KC,4), 128>>>();
    }
    output_kernel<<<NPTS/64, 256>>>(out);
}